// round 1
// baseline (speedup 1.0000x reference)
#include <cuda_runtime.h>
#include <cuda_bf16.h>
#include <math.h>

#define TOKENS 4096
#define DIM 1024
#define HALF 512
#define NUM_KEYS 512
#define TOPK 32

// ---------------- scratch (device globals; no allocation allowed) ----------------
__device__ float g_query[TOKENS * DIM];
__device__ float g_gatepre[TOKENS * DIM];
__device__ float g_s1[TOKENS * NUM_KEYS];
__device__ float g_s2[TOKENS * NUM_KEYS];
__device__ float g_t1v[TOKENS * TOPK];
__device__ int   g_t1i[TOKENS * TOPK];
__device__ float g_t2v[TOKENS * TOPK];
__device__ int   g_t2i[TOKENS * TOPK];
__device__ float g_cv[TOKENS * TOPK];
__device__ int   g_ci[TOKENS * TOPK];
__device__ float g_mid[TOKENS * DIM];

// ---------------- generic TN GEMM: C[m,n] = sum_k A[m,lda]*B[n,ldb] + bias[n] ----
// BM=BN=64, BK=16, 256 threads, 4x4 per thread.
__global__ void gemm_tn(const float* __restrict__ A, int lda,
                        const float* __restrict__ B, int ldb,
                        float* __restrict__ C, int ldc,
                        const float* __restrict__ bias,
                        int K)
{
    __shared__ __align__(16) float As[16][64];
    __shared__ __align__(16) float Bs[16][64];

    const int tid = threadIdx.x;
    const int tx = tid & 15;        // 0..15  -> n
    const int ty = tid >> 4;        // 0..15  -> m
    const int m0 = blockIdx.y * 64;
    const int n0 = blockIdx.x * 64;

    const int lr  = tid >> 2;       // 0..63 row within tile
    const int lc4 = tid & 3;        // 0..3  float4 within 16-k slice

    float acc[4][4];
#pragma unroll
    for (int i = 0; i < 4; i++)
#pragma unroll
        for (int j = 0; j < 4; j++) acc[i][j] = 0.f;

    for (int k0 = 0; k0 < K; k0 += 16) {
        // load A tile: row m0+lr, k k0+lc4*4 .. +3
        float4 av = *reinterpret_cast<const float4*>(&A[(size_t)(m0 + lr) * lda + k0 + lc4 * 4]);
        float4 bv = *reinterpret_cast<const float4*>(&B[(size_t)(n0 + lr) * ldb + k0 + lc4 * 4]);
        As[lc4 * 4 + 0][lr] = av.x;
        As[lc4 * 4 + 1][lr] = av.y;
        As[lc4 * 4 + 2][lr] = av.z;
        As[lc4 * 4 + 3][lr] = av.w;
        Bs[lc4 * 4 + 0][lr] = bv.x;
        Bs[lc4 * 4 + 1][lr] = bv.y;
        Bs[lc4 * 4 + 2][lr] = bv.z;
        Bs[lc4 * 4 + 3][lr] = bv.w;
        __syncthreads();

#pragma unroll
        for (int k = 0; k < 16; k++) {
            float4 a = reinterpret_cast<float4*>(As[k])[ty];
            float4 b = reinterpret_cast<float4*>(Bs[k])[tx];
            float ar[4] = {a.x, a.y, a.z, a.w};
            float br[4] = {b.x, b.y, b.z, b.w};
#pragma unroll
            for (int i = 0; i < 4; i++)
#pragma unroll
                for (int j = 0; j < 4; j++)
                    acc[i][j] = fmaf(ar[i], br[j], acc[i][j]);
        }
        __syncthreads();
    }

#pragma unroll
    for (int i = 0; i < 4; i++) {
        int m = m0 + ty * 4 + i;
        int n = n0 + tx * 4;
        float4 o;
        o.x = acc[i][0]; o.y = acc[i][1]; o.z = acc[i][2]; o.w = acc[i][3];
        if (bias) {
            o.x += bias[n + 0]; o.y += bias[n + 1];
            o.z += bias[n + 2]; o.w += bias[n + 3];
        }
        *reinterpret_cast<float4*>(&C[(size_t)m * ldc + n]) = o;
    }
}

// ---------------- top-32 of 512 per token (iterative argmax) --------------------
__global__ void topk512_kernel(const float* __restrict__ scores,
                               float* __restrict__ topv, int* __restrict__ topi)
{
    const int token = blockIdx.x;
    const int t = threadIdx.x; // 256
    __shared__ float sv[512];
    __shared__ float rv[256];
    __shared__ int   ri[256];

    const float* row = scores + (size_t)token * NUM_KEYS;
    sv[t] = row[t];
    sv[t + 256] = row[t + 256];
    __syncthreads();

    for (int it = 0; it < TOPK; ++it) {
        float v0 = sv[t], v1 = sv[t + 256];
        float bv; int bi;
        if (v1 > v0) { bv = v1; bi = t + 256; } else { bv = v0; bi = t; }
        rv[t] = bv; ri[t] = bi;
        __syncthreads();
#pragma unroll
        for (int s = 128; s > 0; s >>= 1) {
            if (t < s) {
                float ov = rv[t + s]; int oi = ri[t + s];
                if (ov > rv[t] || (ov == rv[t] && oi < ri[t])) { rv[t] = ov; ri[t] = oi; }
            }
            __syncthreads();
        }
        if (t == 0) {
            int b = ri[0];
            topv[(size_t)token * TOPK + it] = rv[0];
            topi[(size_t)token * TOPK + it] = b;
            sv[b] = -INFINITY;
        }
        __syncthreads();
    }
}

// ---------------- combine 32x32 candidates, top-32 of 1024 ----------------------
__global__ void combine_topk_kernel(const float* __restrict__ t1v, const int* __restrict__ t1i,
                                    const float* __restrict__ t2v, const int* __restrict__ t2i,
                                    float* __restrict__ outv, int* __restrict__ outi)
{
    const int token = blockIdx.x;
    const int t = threadIdx.x; // 256
    __shared__ float s1[TOPK], s2[TOPK];
    __shared__ int   i1[TOPK], i2[TOPK];
    __shared__ float cv[1024];
    __shared__ float rv[256];
    __shared__ int   ri[256];

    if (t < TOPK) {
        s1[t] = t1v[(size_t)token * TOPK + t];
        s2[t] = t2v[(size_t)token * TOPK + t];
        i1[t] = t1i[(size_t)token * TOPK + t];
        i2[t] = t2i[(size_t)token * TOPK + t];
    }
    __syncthreads();
#pragma unroll
    for (int i = 0; i < 4; i++) {
        int p = t + i * 256;
        cv[p] = s1[p >> 5] + s2[p & 31];
    }
    __syncthreads();

    for (int it = 0; it < TOPK; ++it) {
        float bv = cv[t]; int bi = t;
#pragma unroll
        for (int i = 1; i < 4; i++) {
            int p = t + i * 256;
            float v = cv[p];
            if (v > bv) { bv = v; bi = p; }  // p ascending -> keeps lowest idx on ties
        }
        rv[t] = bv; ri[t] = bi;
        __syncthreads();
#pragma unroll
        for (int s = 128; s > 0; s >>= 1) {
            if (t < s) {
                float ov = rv[t + s]; int oi = ri[t + s];
                if (ov > rv[t] || (ov == rv[t] && oi < ri[t])) { rv[t] = ov; ri[t] = oi; }
            }
            __syncthreads();
        }
        if (t == 0) {
            int p = ri[0];
            outv[(size_t)token * TOPK + it] = rv[0];
            outi[(size_t)token * TOPK + it] = i1[p >> 5] * NUM_KEYS + i2[p & 31];
            cv[p] = -INFINITY;
        }
        __syncthreads();
    }
}

// ---------------- softmax + gather + silu gate ----------------------------------
__global__ void gather_kernel(const float* __restrict__ topv, const int* __restrict__ topi,
                              const float* __restrict__ values,
                              const float* __restrict__ gatepre,
                              float* __restrict__ mid)
{
    const int token = blockIdx.x;
    const int t = threadIdx.x; // 256
    __shared__ float w[TOPK];
    __shared__ int   id[TOPK];

    if (t < TOPK) {
        id[t] = topi[(size_t)token * TOPK + t];
        w[t]  = topv[(size_t)token * TOPK + t] * (1.0f / 32.0f); // /sqrt(1024)
    }
    __syncthreads();
    if (t < 32) {
        // softmax over 32 within one warp
        float v = w[t];
        float mx = v;
#pragma unroll
        for (int s = 16; s > 0; s >>= 1) mx = fmaxf(mx, __shfl_xor_sync(0xffffffffu, mx, s));
        float e = expf(v - mx);
        float sum = e;
#pragma unroll
        for (int s = 16; s > 0; s >>= 1) sum += __shfl_xor_sync(0xffffffffu, sum, s);
        w[t] = e / sum;
    }
    __syncthreads();

    float acc0 = 0.f, acc1 = 0.f, acc2 = 0.f, acc3 = 0.f;
#pragma unroll 4
    for (int k = 0; k < TOPK; ++k) {
        float wk = w[k];
        const float* row = values + (size_t)id[k] * DIM;
        acc0 = fmaf(wk, __ldg(&row[t]),       acc0);
        acc1 = fmaf(wk, __ldg(&row[t + 256]), acc1);
        acc2 = fmaf(wk, __ldg(&row[t + 512]), acc2);
        acc3 = fmaf(wk, __ldg(&row[t + 768]), acc3);
    }
    const float* gp = gatepre + (size_t)token * DIM;
    float* mo = mid + (size_t)token * DIM;
    float g0 = gp[t];       mo[t]       = acc0 * (g0 / (1.f + expf(-g0)));
    float g1 = gp[t + 256]; mo[t + 256] = acc1 * (g1 / (1.f + expf(-g1)));
    float g2 = gp[t + 512]; mo[t + 512] = acc2 * (g2 / (1.f + expf(-g2)));
    float g3 = gp[t + 768]; mo[t + 768] = acc3 * (g3 / (1.f + expf(-g3)));
}

// ---------------- launch ---------------------------------------------------------
extern "C" void kernel_launch(void* const* d_in, const int* in_sizes, int n_in,
                              void* d_out, int out_size)
{
    const float* x      = (const float*)d_in[0];
    const float* ke1    = (const float*)d_in[1];
    const float* ke2    = (const float*)d_in[2];
    const float* values = (const float*)d_in[3];
    const float* Wq     = (const float*)d_in[4];
    const float* bq     = (const float*)d_in[5];
    const float* Wg     = (const float*)d_in[6];
    const float* bg     = (const float*)d_in[7];
    const float* Wo     = (const float*)d_in[8];
    const float* bo     = (const float*)d_in[9];
    float* out = (float*)d_out;

    float *query, *gatepre, *s1, *s2, *t1v, *t2v, *cv, *mid;
    int *t1i, *t2i, *ci;
    cudaGetSymbolAddress((void**)&query,   g_query);
    cudaGetSymbolAddress((void**)&gatepre, g_gatepre);
    cudaGetSymbolAddress((void**)&s1,      g_s1);
    cudaGetSymbolAddress((void**)&s2,      g_s2);
    cudaGetSymbolAddress((void**)&t1v,     g_t1v);
    cudaGetSymbolAddress((void**)&t1i,     g_t1i);
    cudaGetSymbolAddress((void**)&t2v,     g_t2v);
    cudaGetSymbolAddress((void**)&t2i,     g_t2i);
    cudaGetSymbolAddress((void**)&cv,      g_cv);
    cudaGetSymbolAddress((void**)&ci,      g_ci);
    cudaGetSymbolAddress((void**)&mid,     g_mid);

    dim3 blk(256);
    // query = x @ Wq^T + bq   [4096,1024]
    gemm_tn<<<dim3(DIM / 64, TOKENS / 64), blk>>>(x, DIM, Wq, DIM, query, DIM, bq, DIM);
    // gatepre = x @ Wg^T + bg
    gemm_tn<<<dim3(DIM / 64, TOKENS / 64), blk>>>(x, DIM, Wg, DIM, gatepre, DIM, bg, DIM);
    // scores1 = q1 @ ke1^T   [4096,512], q1 = query[:, :512]
    gemm_tn<<<dim3(NUM_KEYS / 64, TOKENS / 64), blk>>>(query, DIM, ke1, HALF, s1, NUM_KEYS, nullptr, HALF);
    // scores2 = q2 @ ke2^T
    gemm_tn<<<dim3(NUM_KEYS / 64, TOKENS / 64), blk>>>(query + HALF, DIM, ke2, HALF, s2, NUM_KEYS, nullptr, HALF);

    topk512_kernel<<<TOKENS, blk>>>(s1, t1v, t1i);
    topk512_kernel<<<TOKENS, blk>>>(s2, t2v, t2i);
    combine_topk_kernel<<<TOKENS, blk>>>(t1v, t1i, t2v, t2i, cv, ci);
    gather_kernel<<<TOKENS, blk>>>(cv, ci, values, gatepre, mid);

    // out = mid @ Wo^T + bo
    gemm_tn<<<dim3(DIM / 64, TOKENS / 64), blk>>>(mid, DIM, Wo, DIM, out, DIM, bo, DIM);
}

// round 2
// speedup vs baseline: 1.6717x; 1.6717x over previous
#include <cuda_runtime.h>
#include <cuda_bf16.h>
#include <math.h>

#define TOKENS 4096
#define DIM 1024
#define HALF 512
#define NUM_KEYS 512
#define TOPK 32

#define BM 128
#define BN 128
#define BK 8

// ---------------- scratch (device globals; no allocation allowed) ----------------
__device__ float g_query[TOKENS * DIM];
__device__ float g_gatepre[TOKENS * DIM];
__device__ float g_s1[TOKENS * NUM_KEYS];
__device__ float g_s2[TOKENS * NUM_KEYS];
__device__ float g_t1v[TOKENS * TOPK];
__device__ int   g_t1i[TOKENS * TOPK];
__device__ float g_t2v[TOKENS * TOPK];
__device__ int   g_t2i[TOKENS * TOPK];
__device__ float g_mid[TOKENS * DIM];

// ---------------- TN GEMM: C[m,n] = sum_k A[m,*]*B[n,*] + bias[n] ----------------
// BM=BN=128, BK=8, 256 threads, 8x8 per thread, double-buffered smem.
__global__ __launch_bounds__(256, 2)
void gemm_tn2(const float* __restrict__ A, int lda,
              const float* __restrict__ B, int ldb,
              float* __restrict__ C, int ldc,
              const float* __restrict__ bias,
              int K)
{
    __shared__ __align__(16) float As[2][BK][BM];
    __shared__ __align__(16) float Bs[2][BK][BN];

    const int tid = threadIdx.x;
    const int m0 = blockIdx.y * BM;
    const int n0 = blockIdx.x * BN;

    // load mapping: thread -> one float4 of A and one of B per stage
    const int lrow = tid >> 1;         // 0..127
    const int lk4  = (tid & 1) * 4;    // 0 or 4
    const float* Aload = A + (size_t)(m0 + lrow) * lda + lk4;
    const float* Bload = B + (size_t)(n0 + lrow) * ldb + lk4;

    // compute mapping
    const int tx = tid & 15;           // n
    const int ty = tid >> 4;           // m

    float acc[8][8];
#pragma unroll
    for (int i = 0; i < 8; i++)
#pragma unroll
        for (int j = 0; j < 8; j++) acc[i][j] = 0.f;

    float4 av = *reinterpret_cast<const float4*>(Aload);
    float4 bv = *reinterpret_cast<const float4*>(Bload);
    As[0][lk4 + 0][lrow] = av.x;
    As[0][lk4 + 1][lrow] = av.y;
    As[0][lk4 + 2][lrow] = av.z;
    As[0][lk4 + 3][lrow] = av.w;
    Bs[0][lk4 + 0][lrow] = bv.x;
    Bs[0][lk4 + 1][lrow] = bv.y;
    Bs[0][lk4 + 2][lrow] = bv.z;
    Bs[0][lk4 + 3][lrow] = bv.w;
    __syncthreads();

    const int nstages = K / BK;
    int buf = 0;
    for (int s = 0; s < nstages; ++s) {
        if (s + 1 < nstages) {
            av = *reinterpret_cast<const float4*>(Aload + (size_t)(s + 1) * BK);
            bv = *reinterpret_cast<const float4*>(Bload + (size_t)(s + 1) * BK);
        }
#pragma unroll
        for (int k = 0; k < BK; k++) {
            float4 a0 = *reinterpret_cast<const float4*>(&As[buf][k][ty * 4]);
            float4 a1 = *reinterpret_cast<const float4*>(&As[buf][k][64 + ty * 4]);
            float4 b0 = *reinterpret_cast<const float4*>(&Bs[buf][k][tx * 4]);
            float4 b1 = *reinterpret_cast<const float4*>(&Bs[buf][k][64 + tx * 4]);
            float ar[8] = {a0.x, a0.y, a0.z, a0.w, a1.x, a1.y, a1.z, a1.w};
            float br[8] = {b0.x, b0.y, b0.z, b0.w, b1.x, b1.y, b1.z, b1.w};
#pragma unroll
            for (int i = 0; i < 8; i++)
#pragma unroll
                for (int j = 0; j < 8; j++)
                    acc[i][j] = fmaf(ar[i], br[j], acc[i][j]);
        }
        if (s + 1 < nstages) {
            int nb = buf ^ 1;
            As[nb][lk4 + 0][lrow] = av.x;
            As[nb][lk4 + 1][lrow] = av.y;
            As[nb][lk4 + 2][lrow] = av.z;
            As[nb][lk4 + 3][lrow] = av.w;
            Bs[nb][lk4 + 0][lrow] = bv.x;
            Bs[nb][lk4 + 1][lrow] = bv.y;
            Bs[nb][lk4 + 2][lrow] = bv.z;
            Bs[nb][lk4 + 3][lrow] = bv.w;
        }
        __syncthreads();
        buf ^= 1;
    }

    // epilogue
    const int nc0 = n0 + tx * 4;
    const int nc1 = n0 + 64 + tx * 4;
    float4 bb0 = make_float4(0.f, 0.f, 0.f, 0.f);
    float4 bb1 = make_float4(0.f, 0.f, 0.f, 0.f);
    if (bias) {
        bb0 = *reinterpret_cast<const float4*>(&bias[nc0]);
        bb1 = *reinterpret_cast<const float4*>(&bias[nc1]);
    }
#pragma unroll
    for (int i = 0; i < 8; i++) {
        int m = m0 + ((i < 4) ? (ty * 4 + i) : (64 + ty * 4 + i - 4));
        float* Crow = C + (size_t)m * ldc;
        float4 o0 = make_float4(acc[i][0] + bb0.x, acc[i][1] + bb0.y,
                                acc[i][2] + bb0.z, acc[i][3] + bb0.w);
        float4 o1 = make_float4(acc[i][4] + bb1.x, acc[i][5] + bb1.y,
                                acc[i][6] + bb1.z, acc[i][7] + bb1.w);
        *reinterpret_cast<float4*>(&Crow[nc0]) = o0;
        *reinterpret_cast<float4*>(&Crow[nc1]) = o1;
    }
}

// ---------------- warp-per-(token,half) top-32 of 512 ---------------------------
__global__ void topk_warp_kernel(const float* __restrict__ s1, const float* __restrict__ s2,
                                 float* __restrict__ t1v, int* __restrict__ t1i,
                                 float* __restrict__ t2v, int* __restrict__ t2i)
{
    int g = (blockIdx.x * blockDim.x + threadIdx.x) >> 5;   // 0 .. 2*TOKENS-1
    int lane = threadIdx.x & 31;
    int token = g >> 1;
    int which = g & 1;
    const float* src = (which ? s2 : s1) + (size_t)token * NUM_KEYS;
    float* outv = (which ? t2v : t1v) + (size_t)token * TOPK;
    int*   outi = (which ? t2i : t1i) + (size_t)token * TOPK;

    float v[16];
#pragma unroll
    for (int j = 0; j < 16; j++) v[j] = src[j * 32 + lane];

    float lm = v[0]; int lj = 0;
#pragma unroll
    for (int j = 1; j < 16; j++)
        if (v[j] > lm) { lm = v[j]; lj = j; }

    for (int it = 0; it < TOPK; ++it) {
        float bv = lm;
        int bi = lj * 32 + lane;
#pragma unroll
        for (int s = 16; s > 0; s >>= 1) {
            float ov = __shfl_xor_sync(0xffffffffu, bv, s);
            int   oi = __shfl_xor_sync(0xffffffffu, bi, s);
            if (ov > bv || (ov == bv && oi < bi)) { bv = ov; bi = oi; }
        }
        if (lane == 0) { outv[it] = bv; outi[it] = bi; }
        if ((bi & 31) == lane) {
            int jd = bi >> 5;
#pragma unroll
            for (int j = 0; j < 16; j++)
                if (j == jd) v[j] = -INFINITY;
            lm = -INFINITY; lj = 0;
#pragma unroll
            for (int j = 0; j < 16; j++)
                if (v[j] > lm) { lm = v[j]; lj = j; }
        }
    }
}

// ---------------- fused: combine 32x32 topk + softmax + gather + silu gate ------
__global__ void combine_gather_kernel(const float* __restrict__ t1v, const int* __restrict__ t1i,
                                      const float* __restrict__ t2v, const int* __restrict__ t2i,
                                      const float* __restrict__ values,
                                      const float* __restrict__ gatepre,
                                      float* __restrict__ mid)
{
    const int token = blockIdx.x;
    const int tid = threadIdx.x;      // 256
    const int lane = tid & 31;
    const int wid = tid >> 5;

    __shared__ float s1v[TOPK], s2v[TOPK];
    __shared__ int   s1i[TOPK], s2i[TOPK];
    __shared__ float w[TOPK];
    __shared__ int   id[TOPK];

    if (tid < TOPK) {
        s1v[tid] = t1v[(size_t)token * TOPK + tid];
        s2v[tid] = t2v[(size_t)token * TOPK + tid];
        s1i[tid] = t1i[(size_t)token * TOPK + tid];
        s2i[tid] = t2i[(size_t)token * TOPK + tid];
    }
    __syncthreads();

    if (wid == 0) {
        // lane holds candidates p = a*32 + lane, a = 0..31
        float c[32];
        float s2l = s2v[lane];
#pragma unroll
        for (int a = 0; a < 32; a++) c[a] = s1v[a] + s2l;

        float lm = c[0]; int la = 0;
#pragma unroll
        for (int a = 1; a < 32; a++)
            if (c[a] > lm) { lm = c[a]; la = a; }

        for (int it = 0; it < TOPK; ++it) {
            float bv = lm;
            int bp = la * 32 + lane;
#pragma unroll
            for (int s = 16; s > 0; s >>= 1) {
                float ov = __shfl_xor_sync(0xffffffffu, bv, s);
                int   op = __shfl_xor_sync(0xffffffffu, bp, s);
                if (ov > bv || (ov == bv && op < bp)) { bv = ov; bp = op; }
            }
            if (lane == 0) {
                w[it] = bv;
                id[it] = s1i[bp >> 5] * NUM_KEYS + s2i[bp & 31];
            }
            if ((bp & 31) == lane) {
                int ad = bp >> 5;
#pragma unroll
                for (int a = 0; a < 32; a++)
                    if (a == ad) c[a] = -INFINITY;
                lm = -INFINITY; la = 0;
#pragma unroll
                for (int a = 0; a < 32; a++)
                    if (c[a] > lm) { lm = c[a]; la = a; }
            }
            __syncwarp();
        }
        // softmax over the 32 selected (scores / sqrt(1024) = /32)
        float v = w[lane] * (1.0f / 32.0f);
        float mx = v;
#pragma unroll
        for (int s = 16; s > 0; s >>= 1) mx = fmaxf(mx, __shfl_xor_sync(0xffffffffu, mx, s));
        float e = expf(v - mx);
        float sum = e;
#pragma unroll
        for (int s = 16; s > 0; s >>= 1) sum += __shfl_xor_sync(0xffffffffu, sum, s);
        __syncwarp();
        w[lane] = e / sum;
    }
    __syncthreads();

    // gather: each thread owns one float4 column chunk
    float4 acc = make_float4(0.f, 0.f, 0.f, 0.f);
#pragma unroll 8
    for (int k = 0; k < TOPK; ++k) {
        float wk = w[k];
        const float4* row = reinterpret_cast<const float4*>(values + (size_t)id[k] * DIM);
        float4 r = __ldg(&row[tid]);
        acc.x = fmaf(wk, r.x, acc.x);
        acc.y = fmaf(wk, r.y, acc.y);
        acc.z = fmaf(wk, r.z, acc.z);
        acc.w = fmaf(wk, r.w, acc.w);
    }
    float4 gduck = reinterpret_cast<const float4*>(gatepre + (size_t)token * DIM)[tid];
    float4 o;
    o.x = acc.x * (gduck.x / (1.f + expf(-gduck.x)));
    o.y = acc.y * (gduck.y / (1.f + expf(-gduck.y)));
    o.z = acc.z * (gduck.z / (1.f + expf(-gduck.z)));
    o.w = acc.w * (gduck.w / (1.f + expf(-gduck.w)));
    reinterpret_cast<float4*>(mid + (size_t)token * DIM)[tid] = o;
}

// ---------------- launch ---------------------------------------------------------
extern "C" void kernel_launch(void* const* d_in, const int* in_sizes, int n_in,
                              void* d_out, int out_size)
{
    const float* x      = (const float*)d_in[0];
    const float* ke1    = (const float*)d_in[1];
    const float* ke2    = (const float*)d_in[2];
    const float* values = (const float*)d_in[3];
    const float* Wq     = (const float*)d_in[4];
    const float* bq     = (const float*)d_in[5];
    const float* Wg     = (const float*)d_in[6];
    const float* bg     = (const float*)d_in[7];
    const float* Wo     = (const float*)d_in[8];
    const float* bo     = (const float*)d_in[9];
    float* out = (float*)d_out;

    float *query, *gatepre, *s1, *s2, *t1v, *t2v, *mid;
    int *t1i, *t2i;
    cudaGetSymbolAddress((void**)&query,   g_query);
    cudaGetSymbolAddress((void**)&gatepre, g_gatepre);
    cudaGetSymbolAddress((void**)&s1,      g_s1);
    cudaGetSymbolAddress((void**)&s2,      g_s2);
    cudaGetSymbolAddress((void**)&t1v,     g_t1v);
    cudaGetSymbolAddress((void**)&t1i,     g_t1i);
    cudaGetSymbolAddress((void**)&t2v,     g_t2v);
    cudaGetSymbolAddress((void**)&t2i,     g_t2i);
    cudaGetSymbolAddress((void**)&mid,     g_mid);

    dim3 blk(256);
    // query = x @ Wq^T + bq   [4096,1024]
    gemm_tn2<<<dim3(DIM / BN, TOKENS / BM), blk>>>(x, DIM, Wq, DIM, query, DIM, bq, DIM);
    // scores1 = q1 @ ke1^T   [4096,512]
    gemm_tn2<<<dim3(NUM_KEYS / BN, TOKENS / BM), blk>>>(query, DIM, ke1, HALF, s1, NUM_KEYS, nullptr, HALF);
    // scores2 = q2 @ ke2^T
    gemm_tn2<<<dim3(NUM_KEYS / BN, TOKENS / BM), blk>>>(query + HALF, DIM, ke2, HALF, s2, NUM_KEYS, nullptr, HALF);
    // gatepre = x @ Wg^T + bg  (independent of scores; after them to overlap tails)
    gemm_tn2<<<dim3(DIM / BN, TOKENS / BM), blk>>>(x, DIM, Wg, DIM, gatepre, DIM, bg, DIM);

    // top-32 of each 512-score row, one warp per (token, half)
    topk_warp_kernel<<<(2 * TOKENS) / 8, blk>>>(s1, s2, t1v, t1i, t2v, t2i);

    // combine + softmax + gather + gate
    combine_gather_kernel<<<TOKENS, blk>>>(t1v, t1i, t2v, t2i, values, gatepre, mid);

    // out = mid @ Wo^T + bo
    gemm_tn2<<<dim3(DIM / BN, TOKENS / BM), blk>>>(mid, DIM, Wo, DIM, out, DIM, bo, DIM);
}

// round 3
// speedup vs baseline: 2.2238x; 1.3302x over previous
#include <cuda_runtime.h>
#include <cuda_bf16.h>
#include <math.h>

#define TOKENS 4096
#define DIM 1024
#define HALF 512
#define NUM_KEYS 512
#define TOPK 32

#define BM 128
#define BN 128
#define BK 8

// mma kernel tile config
#define MBK 16
#define PK  20   // smem k-pitch (floats), conflict-free for frag loads

// ---------------- scratch (device globals; no allocation allowed) ----------------
__device__ float g_query[TOKENS * DIM];
__device__ float g_gatepre[TOKENS * DIM];
__device__ float g_s1[TOKENS * NUM_KEYS];
__device__ float g_s2[TOKENS * NUM_KEYS];
__device__ float g_t1v[TOKENS * TOPK];
__device__ int   g_t1i[TOKENS * TOPK];
__device__ float g_t2v[TOKENS * TOPK];
__device__ int   g_t2i[TOKENS * TOPK];
__device__ float g_mid[TOKENS * DIM];

// ================= fp32 SIMT TN GEMM (exact path: Wq, scores) ====================
__global__ __launch_bounds__(256, 2)
void gemm_tn2(const float* __restrict__ A, int lda,
              const float* __restrict__ B, int ldb,
              float* __restrict__ C, int ldc,
              const float* __restrict__ bias,
              int K)
{
    __shared__ __align__(16) float As[2][BK][BM];
    __shared__ __align__(16) float Bs[2][BK][BN];

    const int tid = threadIdx.x;
    const int m0 = blockIdx.y * BM;
    const int n0 = blockIdx.x * BN;

    const int lrow = tid >> 1;
    const int lk4  = (tid & 1) * 4;
    const float* Aload = A + (size_t)(m0 + lrow) * lda + lk4;
    const float* Bload = B + (size_t)(n0 + lrow) * ldb + lk4;

    const int tx = tid & 15;
    const int ty = tid >> 4;

    float acc[8][8];
#pragma unroll
    for (int i = 0; i < 8; i++)
#pragma unroll
        for (int j = 0; j < 8; j++) acc[i][j] = 0.f;

    float4 av = *reinterpret_cast<const float4*>(Aload);
    float4 bv = *reinterpret_cast<const float4*>(Bload);
    As[0][lk4 + 0][lrow] = av.x;
    As[0][lk4 + 1][lrow] = av.y;
    As[0][lk4 + 2][lrow] = av.z;
    As[0][lk4 + 3][lrow] = av.w;
    Bs[0][lk4 + 0][lrow] = bv.x;
    Bs[0][lk4 + 1][lrow] = bv.y;
    Bs[0][lk4 + 2][lrow] = bv.z;
    Bs[0][lk4 + 3][lrow] = bv.w;
    __syncthreads();

    const int nstages = K / BK;
    int buf = 0;
    for (int s = 0; s < nstages; ++s) {
        if (s + 1 < nstages) {
            av = *reinterpret_cast<const float4*>(Aload + (size_t)(s + 1) * BK);
            bv = *reinterpret_cast<const float4*>(Bload + (size_t)(s + 1) * BK);
        }
#pragma unroll
        for (int k = 0; k < BK; k++) {
            float4 a0 = *reinterpret_cast<const float4*>(&As[buf][k][ty * 4]);
            float4 a1 = *reinterpret_cast<const float4*>(&As[buf][k][64 + ty * 4]);
            float4 b0 = *reinterpret_cast<const float4*>(&Bs[buf][k][tx * 4]);
            float4 b1 = *reinterpret_cast<const float4*>(&Bs[buf][k][64 + tx * 4]);
            float ar[8] = {a0.x, a0.y, a0.z, a0.w, a1.x, a1.y, a1.z, a1.w};
            float br[8] = {b0.x, b0.y, b0.z, b0.w, b1.x, b1.y, b1.z, b1.w};
#pragma unroll
            for (int i = 0; i < 8; i++)
#pragma unroll
                for (int j = 0; j < 8; j++)
                    acc[i][j] = fmaf(ar[i], br[j], acc[i][j]);
        }
        if (s + 1 < nstages) {
            int nb = buf ^ 1;
            As[nb][lk4 + 0][lrow] = av.x;
            As[nb][lk4 + 1][lrow] = av.y;
            As[nb][lk4 + 2][lrow] = av.z;
            As[nb][lk4 + 3][lrow] = av.w;
            Bs[nb][lk4 + 0][lrow] = bv.x;
            Bs[nb][lk4 + 1][lrow] = bv.y;
            Bs[nb][lk4 + 2][lrow] = bv.z;
            Bs[nb][lk4 + 3][lrow] = bv.w;
        }
        __syncthreads();
        buf ^= 1;
    }

    const int nc0 = n0 + tx * 4;
    const int nc1 = n0 + 64 + tx * 4;
    float4 bb0 = make_float4(0.f, 0.f, 0.f, 0.f);
    float4 bb1 = make_float4(0.f, 0.f, 0.f, 0.f);
    if (bias) {
        bb0 = *reinterpret_cast<const float4*>(&bias[nc0]);
        bb1 = *reinterpret_cast<const float4*>(&bias[nc1]);
    }
#pragma unroll
    for (int i = 0; i < 8; i++) {
        int m = m0 + ((i < 4) ? (ty * 4 + i) : (64 + ty * 4 + i - 4));
        float* Crow = C + (size_t)m * ldc;
        float4 o0 = make_float4(acc[i][0] + bb0.x, acc[i][1] + bb0.y,
                                acc[i][2] + bb0.z, acc[i][3] + bb0.w);
        float4 o1 = make_float4(acc[i][4] + bb1.x, acc[i][5] + bb1.y,
                                acc[i][6] + bb1.z, acc[i][7] + bb1.w);
        *reinterpret_cast<float4*>(&Crow[nc0]) = o0;
        *reinterpret_cast<float4*>(&Crow[nc1]) = o1;
    }
}

// ================= tf32 tensor-core TN GEMM (smooth path: Wg, Wo) ================
__device__ __forceinline__ unsigned f2tf(float x) {
    unsigned r;
    asm("cvt.rna.tf32.f32 %0, %1;" : "=r"(r) : "f"(x));
    return r;
}
__device__ __forceinline__ void mma8(float* c, const unsigned* a, const unsigned* b) {
    asm volatile("mma.sync.aligned.m16n8k8.row.col.f32.tf32.tf32.f32 "
                 "{%0,%1,%2,%3}, {%4,%5,%6,%7}, {%8,%9}, {%0,%1,%2,%3};"
                 : "+f"(c[0]), "+f"(c[1]), "+f"(c[2]), "+f"(c[3])
                 : "r"(a[0]), "r"(a[1]), "r"(a[2]), "r"(a[3]),
                   "r"(b[0]), "r"(b[1]));
}
__device__ __forceinline__ void cp16(unsigned sdst, const void* gsrc) {
    asm volatile("cp.async.cg.shared.global [%0], [%1], 16;" :: "r"(sdst), "l"(gsrc));
}

__global__ __launch_bounds__(256)
void gemm_mma_tf32(const float* __restrict__ A, int lda,
                   const float* __restrict__ B, int ldb,
                   float* __restrict__ C, int ldc,
                   const float* __restrict__ bias, int K)
{
    __shared__ float As[2][BM][PK];
    __shared__ float Bs[2][BN][PK];

    const int tid  = threadIdx.x;
    const int lane = tid & 31, warp = tid >> 5;
    const int gid  = lane >> 2, tig = lane & 3;
    const int wm = (warp & 1) * 64;     // warp m-offset (2x4 warp grid)
    const int wn = (warp >> 1) * 32;    // warp n-offset
    const int m0 = blockIdx.y * BM, n0 = blockIdx.x * BN;

    // staging mapping: each thread copies 2 float4 of A and 2 of B per stage
    const int srow = tid >> 2;          // 0..63
    const int skc  = (tid & 3) * 4;     // 0,4,8,12

    const float* Ag = A + (size_t)(m0 + srow) * lda + skc;
    const float* Bg = B + (size_t)(n0 + srow) * ldb + skc;
    const unsigned sA0 = (unsigned)__cvta_generic_to_shared(&As[0][srow][skc]);
    const unsigned sB0 = (unsigned)__cvta_generic_to_shared(&Bs[0][srow][skc]);
    const unsigned bufStride = (unsigned)(sizeof(float) * BM * PK);
    const unsigned rowHop    = (unsigned)(sizeof(float) * 64 * PK);

    float acc[4][4][4];
#pragma unroll
    for (int mi = 0; mi < 4; mi++)
#pragma unroll
        for (int ni = 0; ni < 4; ni++)
#pragma unroll
            for (int r = 0; r < 4; r++) acc[mi][ni][r] = 0.f;

    // prologue: stage 0
    {
        cp16(sA0,          Ag);
        cp16(sA0 + rowHop, Ag + (size_t)64 * lda);
        cp16(sB0,          Bg);
        cp16(sB0 + rowHop, Bg + (size_t)64 * ldb);
        asm volatile("cp.async.commit_group;");
    }

    const int nst = K / MBK;
    int buf = 0;
    for (int s = 0; s < nst; ++s) {
        if (s + 1 < nst) {
            const float* a = Ag + (size_t)(s + 1) * MBK;
            const float* b = Bg + (size_t)(s + 1) * MBK;
            unsigned off = (buf ^ 1) * bufStride;
            cp16(sA0 + off,          a);
            cp16(sA0 + off + rowHop, a + (size_t)64 * lda);
            cp16(sB0 + off,          b);
            cp16(sB0 + off + rowHop, b + (size_t)64 * ldb);
            asm volatile("cp.async.commit_group;");
            asm volatile("cp.async.wait_group 1;");
        } else {
            asm volatile("cp.async.wait_group 0;");
        }
        __syncthreads();

#pragma unroll
        for (int kk = 0; kk < 2; ++kk) {
            const int k0 = kk * 8;
            unsigned a[4][4], b[4][2];
#pragma unroll
            for (int mi = 0; mi < 4; ++mi) {
                int r0 = wm + mi * 16 + gid;
                a[mi][0] = f2tf(As[buf][r0][k0 + tig]);
                a[mi][1] = f2tf(As[buf][r0 + 8][k0 + tig]);
                a[mi][2] = f2tf(As[buf][r0][k0 + tig + 4]);
                a[mi][3] = f2tf(As[buf][r0 + 8][k0 + tig + 4]);
            }
#pragma unroll
            for (int ni = 0; ni < 4; ++ni) {
                int r = wn + ni * 8 + gid;
                b[ni][0] = f2tf(Bs[buf][r][k0 + tig]);
                b[ni][1] = f2tf(Bs[buf][r][k0 + tig + 4]);
            }
#pragma unroll
            for (int mi = 0; mi < 4; ++mi)
#pragma unroll
                for (int ni = 0; ni < 4; ++ni)
                    mma8(acc[mi][ni], a[mi], b[ni]);
        }
        __syncthreads();
        buf ^= 1;
    }

    // epilogue
#pragma unroll
    for (int ni = 0; ni < 4; ++ni) {
        int c0 = n0 + wn + ni * 8 + tig * 2;
        float2 bb = make_float2(0.f, 0.f);
        if (bias) bb = *reinterpret_cast<const float2*>(&bias[c0]);
#pragma unroll
        for (int mi = 0; mi < 4; ++mi) {
            int r = m0 + wm + mi * 16 + gid;
            *reinterpret_cast<float2*>(&C[(size_t)r * ldc + c0]) =
                make_float2(acc[mi][ni][0] + bb.x, acc[mi][ni][1] + bb.y);
            *reinterpret_cast<float2*>(&C[(size_t)(r + 8) * ldc + c0]) =
                make_float2(acc[mi][ni][2] + bb.x, acc[mi][ni][3] + bb.y);
        }
    }
}

// ---------------- warp-per-(token,half) top-32 of 512 ---------------------------
__global__ void topk_warp_kernel(const float* __restrict__ s1, const float* __restrict__ s2,
                                 float* __restrict__ t1v, int* __restrict__ t1i,
                                 float* __restrict__ t2v, int* __restrict__ t2i)
{
    int g = (blockIdx.x * blockDim.x + threadIdx.x) >> 5;
    int lane = threadIdx.x & 31;
    int token = g >> 1;
    int which = g & 1;
    const float* src = (which ? s2 : s1) + (size_t)token * NUM_KEYS;
    float* outv = (which ? t2v : t1v) + (size_t)token * TOPK;
    int*   outi = (which ? t2i : t1i) + (size_t)token * TOPK;

    float v[16];
#pragma unroll
    for (int j = 0; j < 16; j++) v[j] = src[j * 32 + lane];

    float lm = v[0]; int lj = 0;
#pragma unroll
    for (int j = 1; j < 16; j++)
        if (v[j] > lm) { lm = v[j]; lj = j; }

    for (int it = 0; it < TOPK; ++it) {
        float bv = lm;
        int bi = lj * 32 + lane;
#pragma unroll
        for (int s = 16; s > 0; s >>= 1) {
            float ov = __shfl_xor_sync(0xffffffffu, bv, s);
            int   oi = __shfl_xor_sync(0xffffffffu, bi, s);
            if (ov > bv || (ov == bv && oi < bi)) { bv = ov; bi = oi; }
        }
        if (lane == 0) { outv[it] = bv; outi[it] = bi; }
        if ((bi & 31) == lane) {
            int jd = bi >> 5;
#pragma unroll
            for (int j = 0; j < 16; j++)
                if (j == jd) v[j] = -INFINITY;
            lm = -INFINITY; lj = 0;
#pragma unroll
            for (int j = 0; j < 16; j++)
                if (v[j] > lm) { lm = v[j]; lj = j; }
        }
    }
}

// ---------------- fused: combine 32x32 topk + softmax + gather + silu gate ------
__global__ void combine_gather_kernel(const float* __restrict__ t1v, const int* __restrict__ t1i,
                                      const float* __restrict__ t2v, const int* __restrict__ t2i,
                                      const float* __restrict__ values,
                                      const float* __restrict__ gatepre,
                                      float* __restrict__ mid)
{
    const int token = blockIdx.x;
    const int tid = threadIdx.x;
    const int lane = tid & 31;
    const int wid = tid >> 5;

    __shared__ float s1v[TOPK], s2v[TOPK];
    __shared__ int   s1i[TOPK], s2i[TOPK];
    __shared__ float w[TOPK];
    __shared__ int   id[TOPK];

    if (tid < TOPK) {
        s1v[tid] = t1v[(size_t)token * TOPK + tid];
        s2v[tid] = t2v[(size_t)token * TOPK + tid];
        s1i[tid] = t1i[(size_t)token * TOPK + tid];
        s2i[tid] = t2i[(size_t)token * TOPK + tid];
    }
    __syncthreads();

    if (wid == 0) {
        float c[32];
        float s2l = s2v[lane];
#pragma unroll
        for (int a = 0; a < 32; a++) c[a] = s1v[a] + s2l;

        float lm = c[0]; int la = 0;
#pragma unroll
        for (int a = 1; a < 32; a++)
            if (c[a] > lm) { lm = c[a]; la = a; }

        for (int it = 0; it < TOPK; ++it) {
            float bv = lm;
            int bp = la * 32 + lane;
#pragma unroll
            for (int s = 16; s > 0; s >>= 1) {
                float ov = __shfl_xor_sync(0xffffffffu, bv, s);
                int   op = __shfl_xor_sync(0xffffffffu, bp, s);
                if (ov > bv || (ov == bv && op < bp)) { bv = ov; bp = op; }
            }
            if (lane == 0) {
                w[it] = bv;
                id[it] = s1i[bp >> 5] * NUM_KEYS + s2i[bp & 31];
            }
            if ((bp & 31) == lane) {
                int ad = bp >> 5;
#pragma unroll
                for (int a = 0; a < 32; a++)
                    if (a == ad) c[a] = -INFINITY;
                lm = -INFINITY; la = 0;
#pragma unroll
                for (int a = 0; a < 32; a++)
                    if (c[a] > lm) { lm = c[a]; la = a; }
            }
            __syncwarp();
        }
        float v = w[lane] * (1.0f / 32.0f);
        float mx = v;
#pragma unroll
        for (int s = 16; s > 0; s >>= 1) mx = fmaxf(mx, __shfl_xor_sync(0xffffffffu, mx, s));
        float e = expf(v - mx);
        float sum = e;
#pragma unroll
        for (int s = 16; s > 0; s >>= 1) sum += __shfl_xor_sync(0xffffffffu, sum, s);
        __syncwarp();
        w[lane] = e / sum;
    }
    __syncthreads();

    float4 acc = make_float4(0.f, 0.f, 0.f, 0.f);
#pragma unroll 8
    for (int k = 0; k < TOPK; ++k) {
        float wk = w[k];
        const float4* row = reinterpret_cast<const float4*>(values + (size_t)id[k] * DIM);
        float4 r = __ldg(&row[tid]);
        acc.x = fmaf(wk, r.x, acc.x);
        acc.y = fmaf(wk, r.y, acc.y);
        acc.z = fmaf(wk, r.z, acc.z);
        acc.w = fmaf(wk, r.w, acc.w);
    }
    float4 gduck = reinterpret_cast<const float4*>(gatepre + (size_t)token * DIM)[tid];
    float4 o;
    o.x = acc.x * (gduck.x / (1.f + expf(-gduck.x)));
    o.y = acc.y * (gduck.y / (1.f + expf(-gduck.y)));
    o.z = acc.z * (gduck.z / (1.f + expf(-gduck.z)));
    o.w = acc.w * (gduck.w / (1.f + expf(-gduck.w)));
    reinterpret_cast<float4*>(mid + (size_t)token * DIM)[tid] = o;
}

// ---------------- launch ---------------------------------------------------------
extern "C" void kernel_launch(void* const* d_in, const int* in_sizes, int n_in,
                              void* d_out, int out_size)
{
    const float* x      = (const float*)d_in[0];
    const float* ke1    = (const float*)d_in[1];
    const float* ke2    = (const float*)d_in[2];
    const float* values = (const float*)d_in[3];
    const float* Wq     = (const float*)d_in[4];
    const float* bq     = (const float*)d_in[5];
    const float* Wg     = (const float*)d_in[6];
    const float* bg     = (const float*)d_in[7];
    const float* Wo     = (const float*)d_in[8];
    const float* bo     = (const float*)d_in[9];
    float* out = (float*)d_out;

    float *query, *gatepre, *s1, *s2, *t1v, *t2v, *mid;
    int *t1i, *t2i;
    cudaGetSymbolAddress((void**)&query,   g_query);
    cudaGetSymbolAddress((void**)&gatepre, g_gatepre);
    cudaGetSymbolAddress((void**)&s1,      g_s1);
    cudaGetSymbolAddress((void**)&s2,      g_s2);
    cudaGetSymbolAddress((void**)&t1v,     g_t1v);
    cudaGetSymbolAddress((void**)&t1i,     g_t1i);
    cudaGetSymbolAddress((void**)&t2v,     g_t2v);
    cudaGetSymbolAddress((void**)&t2i,     g_t2i);
    cudaGetSymbolAddress((void**)&mid,     g_mid);

    dim3 blk(256);
    // exact fp32 path (feeds top-k selection): query + scores
    gemm_tn2<<<dim3(DIM / BN, TOKENS / BM), blk>>>(x, DIM, Wq, DIM, query, DIM, bq, DIM);
    gemm_tn2<<<dim3(NUM_KEYS / BN, TOKENS / BM), blk>>>(query, DIM, ke1, HALF, s1, NUM_KEYS, nullptr, HALF);
    gemm_tn2<<<dim3(NUM_KEYS / BN, TOKENS / BM), blk>>>(query + HALF, DIM, ke2, HALF, s2, NUM_KEYS, nullptr, HALF);
    // smooth path (tensor cores, tf32): gate pre-activation
    gemm_mma_tf32<<<dim3(DIM / BN, TOKENS / BM), blk>>>(x, DIM, Wg, DIM, gatepre, DIM, bg, DIM);

    topk_warp_kernel<<<(2 * TOKENS) / 8, blk>>>(s1, s2, t1v, t1i, t2v, t2i);
    combine_gather_kernel<<<TOKENS, blk>>>(t1v, t1i, t2v, t2i, values, gatepre, mid);

    // smooth path (tensor cores, tf32): output projection
    gemm_mma_tf32<<<dim3(DIM / BN, TOKENS / BM), blk>>>(mid, DIM, Wo, DIM, out, DIM, bo, DIM);
}

// round 5
// speedup vs baseline: 2.3589x; 1.0608x over previous
#include <cuda_runtime.h>
#include <cuda_bf16.h>
#include <math.h>

#define TOKENS 4096
#define DIM 1024
#define HALF 512
#define NUM_KEYS 512
#define TOPK 32

#define BM 128
#define BN 128
#define BK 8

// ---------------- scratch (device globals; no allocation allowed) ----------------
__device__ float g_xh[TOKENS * DIM];       // tf32-rounded x
__device__ float g_wgh[DIM * DIM];         // tf32-rounded Wg
__device__ float g_woh[DIM * DIM];         // tf32-rounded Wo
__device__ float g_M[DIM * DIM];           // folded key matrix [1024 keys, 1024 d]
__device__ float g_c[DIM];                 // folded bias per key (2*512)
__device__ float g_scores[TOKENS * DIM];   // [s1 | s2] per token
__device__ float g_gatepre[TOKENS * DIM];
__device__ float g_midh[TOKENS * DIM];
__device__ float g_t1v[TOKENS * TOPK];
__device__ int   g_t1i[TOKENS * TOPK];
__device__ float g_t2v[TOKENS * TOPK];
__device__ int   g_t2i[TOKENS * TOPK];

// ---------------- helpers --------------------------------------------------------
__device__ __forceinline__ unsigned f2tf(float x) {
    unsigned r;
    asm("cvt.rna.tf32.f32 %0, %1;" : "=r"(r) : "f"(x));
    return r;
}
__device__ __forceinline__ float tf32f(float x) { return __uint_as_float(f2tf(x)); }

__device__ __forceinline__ void mma8(float* c, const unsigned* a, const unsigned* b) {
    asm volatile("mma.sync.aligned.m16n8k8.row.col.f32.tf32.tf32.f32 "
                 "{%0,%1,%2,%3}, {%4,%5,%6,%7}, {%8,%9}, {%0,%1,%2,%3};"
                 : "+f"(c[0]), "+f"(c[1]), "+f"(c[2]), "+f"(c[3])
                 : "r"(a[0]), "r"(a[1]), "r"(a[2]), "r"(a[3]),
                   "r"(b[0]), "r"(b[1]));
}
__device__ __forceinline__ void cp16(unsigned sdst, const void* gsrc) {
    asm volatile("cp.async.cg.shared.global [%0], [%1], 16;" :: "r"(sdst), "l"(gsrc));
}

// ---------------- prep: round x, Wg, Wo to tf32 ----------------------------------
#define P4_X ((TOKENS * DIM) / 4)
#define P4_W ((DIM * DIM) / 4)
#define P4_TOT (P4_X + 2 * P4_W)

__global__ void prep_kernel(const float4* __restrict__ x, const float4* __restrict__ Wg,
                            const float4* __restrict__ Wo,
                            float4* __restrict__ xh, float4* __restrict__ wgh,
                            float4* __restrict__ woh)
{
    int i = blockIdx.x * blockDim.x + threadIdx.x;
    if (i >= P4_TOT) return;
    const float4* src; float4* dst; int off;
    if (i < P4_X)            { src = x;  dst = xh;  off = i; }
    else if (i < P4_X + P4_W){ src = Wg; dst = wgh; off = i - P4_X; }
    else                     { src = Wo; dst = woh; off = i - P4_X - P4_W; }
    float4 v = src[off];
    dst[off] = make_float4(tf32f(v.x), tf32f(v.y), tf32f(v.z), tf32f(v.w));
}

// ---------------- bias fold: c[k] = dot(ke_half[k], bq_half) --------------------
__global__ void cfold_kernel(const float* __restrict__ ke1, const float* __restrict__ ke2,
                             const float* __restrict__ bq, float* __restrict__ c)
{
    int w = (blockIdx.x * blockDim.x + threadIdx.x) >> 5;  // key index 0..1023
    int lane = threadIdx.x & 31;
    const float* ke = (w < NUM_KEYS) ? (ke1 + (size_t)w * HALF)
                                     : (ke2 + (size_t)(w - NUM_KEYS) * HALF);
    const float* b  = (w < NUM_KEYS) ? bq : bq + HALF;
    float s = 0.f;
#pragma unroll
    for (int j = 0; j < 16; ++j)
        s = fmaf(ke[lane + j * 32], b[lane + j * 32], s);
#pragma unroll
    for (int sh = 16; sh > 0; sh >>= 1) s += __shfl_xor_sync(0xffffffffu, s, sh);
    if (lane == 0) c[w] = s;
}

// ---------------- M prep (NN GEMM, fp32 exact): M[k,d] = sum_e ke[k,e] Wq[e',d] --
// 64x64 tile, BK=16, 256 threads, 4x4 microtile.
__global__ __launch_bounds__(256)
void mprep_kernel(const float* __restrict__ ke1, const float* __restrict__ ke2,
                  const float* __restrict__ Wq, float* __restrict__ M)
{
    __shared__ __align__(16) float As[16][64];
    __shared__ __align__(16) float Bs[16][64];

    const int tid = threadIdx.x;
    const int m0 = blockIdx.y * 64;   // key rows
    const int n0 = blockIdx.x * 64;   // d cols

    const float* Arow = (m0 < NUM_KEYS) ? (ke1 + (size_t)m0 * HALF)
                                        : (ke2 + (size_t)(m0 - NUM_KEYS) * HALF);
    const int woff = (m0 < NUM_KEYS) ? 0 : HALF;

    const int lr  = tid >> 2;         // 0..63 (A row)
    const int lc4 = (tid & 3) * 4;    // A k-offset
    const int bk  = tid >> 4;         // 0..15 (B k-row)
    const int bn4 = (tid & 15) * 4;   // B n-offset

    const int tx = tid & 15;
    const int ty = tid >> 4;

    float acc[4][4];
#pragma unroll
    for (int i = 0; i < 4; i++)
#pragma unroll
        for (int j = 0; j < 4; j++) acc[i][j] = 0.f;

    for (int k0 = 0; k0 < HALF; k0 += 16) {
        float4 av = *reinterpret_cast<const float4*>(&Arow[(size_t)lr * HALF + k0 + lc4]);
        As[lc4 + 0][lr] = av.x;
        As[lc4 + 1][lr] = av.y;
        As[lc4 + 2][lr] = av.z;
        As[lc4 + 3][lr] = av.w;
        float4 bv = *reinterpret_cast<const float4*>(&Wq[(size_t)(woff + k0 + bk) * DIM + n0 + bn4]);
        *reinterpret_cast<float4*>(&Bs[bk][bn4]) = bv;
        __syncthreads();

#pragma unroll
        for (int k = 0; k < 16; k++) {
            float4 a = reinterpret_cast<float4*>(As[k])[ty];
            float4 b = reinterpret_cast<float4*>(Bs[k])[tx];
            float ar[4] = {a.x, a.y, a.z, a.w};
            float br[4] = {b.x, b.y, b.z, b.w};
#pragma unroll
            for (int i = 0; i < 4; i++)
#pragma unroll
                for (int j = 0; j < 4; j++)
                    acc[i][j] = fmaf(ar[i], br[j], acc[i][j]);
        }
        __syncthreads();
    }

#pragma unroll
    for (int i = 0; i < 4; i++) {
        int m = m0 + ty * 4 + i;
        float4 o = make_float4(acc[i][0], acc[i][1], acc[i][2], acc[i][3]);
        *reinterpret_cast<float4*>(&M[(size_t)m * DIM + n0 + tx * 4]) = o;
    }
}

// ================= fp32 SIMT TN GEMM (exact path: scores) ========================
__global__ __launch_bounds__(256, 2)
void gemm_tn2(const float* __restrict__ A, int lda,
              const float* __restrict__ B, int ldb,
              float* __restrict__ C, int ldc,
              const float* __restrict__ bias,
              int K)
{
    __shared__ __align__(16) float As[2][BK][BM];
    __shared__ __align__(16) float Bs[2][BK][BN];

    const int tid = threadIdx.x;
    const int m0 = blockIdx.y * BM;
    const int n0 = blockIdx.x * BN;

    const int lrow = tid >> 1;
    const int lk4  = (tid & 1) * 4;
    const float* Aload = A + (size_t)(m0 + lrow) * lda + lk4;
    const float* Bload = B + (size_t)(n0 + lrow) * ldb + lk4;

    const int tx = tid & 15;
    const int ty = tid >> 4;

    float acc[8][8];
#pragma unroll
    for (int i = 0; i < 8; i++)
#pragma unroll
        for (int j = 0; j < 8; j++) acc[i][j] = 0.f;

    float4 av = *reinterpret_cast<const float4*>(Aload);
    float4 bv = *reinterpret_cast<const float4*>(Bload);
    As[0][lk4 + 0][lrow] = av.x;
    As[0][lk4 + 1][lrow] = av.y;
    As[0][lk4 + 2][lrow] = av.z;
    As[0][lk4 + 3][lrow] = av.w;
    Bs[0][lk4 + 0][lrow] = bv.x;
    Bs[0][lk4 + 1][lrow] = bv.y;
    Bs[0][lk4 + 2][lrow] = bv.z;
    Bs[0][lk4 + 3][lrow] = bv.w;
    __syncthreads();

    const int nstages = K / BK;
    int buf = 0;
    for (int s = 0; s < nstages; ++s) {
        if (s + 1 < nstages) {
            av = *reinterpret_cast<const float4*>(Aload + (size_t)(s + 1) * BK);
            bv = *reinterpret_cast<const float4*>(Bload + (size_t)(s + 1) * BK);
        }
#pragma unroll
        for (int k = 0; k < BK; k++) {
            float4 a0 = *reinterpret_cast<const float4*>(&As[buf][k][ty * 4]);
            float4 a1 = *reinterpret_cast<const float4*>(&As[buf][k][64 + ty * 4]);
            float4 b0 = *reinterpret_cast<const float4*>(&Bs[buf][k][tx * 4]);
            float4 b1 = *reinterpret_cast<const float4*>(&Bs[buf][k][64 + tx * 4]);
            float ar[8] = {a0.x, a0.y, a0.z, a0.w, a1.x, a1.y, a1.z, a1.w};
            float br[8] = {b0.x, b0.y, b0.z, b0.w, b1.x, b1.y, b1.z, b1.w};
#pragma unroll
            for (int i = 0; i < 8; i++)
#pragma unroll
                for (int j = 0; j < 8; j++)
                    acc[i][j] = fmaf(ar[i], br[j], acc[i][j]);
        }
        if (s + 1 < nstages) {
            int nb = buf ^ 1;
            As[nb][lk4 + 0][lrow] = av.x;
            As[nb][lk4 + 1][lrow] = av.y;
            As[nb][lk4 + 2][lrow] = av.z;
            As[nb][lk4 + 3][lrow] = av.w;
            Bs[nb][lk4 + 0][lrow] = bv.x;
            Bs[nb][lk4 + 1][lrow] = bv.y;
            Bs[nb][lk4 + 2][lrow] = bv.z;
            Bs[nb][lk4 + 3][lrow] = bv.w;
        }
        __syncthreads();
        buf ^= 1;
    }

    const int nc0 = n0 + tx * 4;
    const int nc1 = n0 + 64 + tx * 4;
    float4 bb0 = make_float4(0.f, 0.f, 0.f, 0.f);
    float4 bb1 = make_float4(0.f, 0.f, 0.f, 0.f);
    if (bias) {
        bb0 = *reinterpret_cast<const float4*>(&bias[nc0]);
        bb1 = *reinterpret_cast<const float4*>(&bias[nc1]);
    }
#pragma unroll
    for (int i = 0; i < 8; i++) {
        int m = m0 + ((i < 4) ? (ty * 4 + i) : (64 + ty * 4 + i - 4));
        float* Crow = C + (size_t)m * ldc;
        float4 o0 = make_float4(acc[i][0] + bb0.x, acc[i][1] + bb0.y,
                                acc[i][2] + bb0.z, acc[i][3] + bb0.w);
        float4 o1 = make_float4(acc[i][4] + bb1.x, acc[i][5] + bb1.y,
                                acc[i][6] + bb1.z, acc[i][7] + bb1.w);
        *reinterpret_cast<float4*>(&Crow[nc0]) = o0;
        *reinterpret_cast<float4*>(&Crow[nc1]) = o1;
    }
}

// ================= tf32 tensor-core TN GEMM (pre-rounded operands) ===============
#define MBK 16
#define PK  20
__global__ __launch_bounds__(256)
void gemm_mma_tf32(const float* __restrict__ A, int lda,
                   const float* __restrict__ B, int ldb,
                   float* __restrict__ C, int ldc,
                   const float* __restrict__ bias, int K)
{
    __shared__ float As[2][BM][PK];
    __shared__ float Bs[2][BN][PK];

    const int tid  = threadIdx.x;
    const int lane = tid & 31, warp = tid >> 5;
    const int gid  = lane >> 2, tig = lane & 3;
    const int wm = (warp & 1) * 64;
    const int wn = (warp >> 1) * 32;
    const int m0 = blockIdx.y * BM, n0 = blockIdx.x * BN;

    const int srow = tid >> 1;
    const int scol = (tid & 1) * 8;

    float acc[4][4][4];
#pragma unroll
    for (int mi = 0; mi < 4; mi++)
#pragma unroll
        for (int ni = 0; ni < 4; ni++)
#pragma unroll
            for (int r = 0; r < 4; r++) acc[mi][ni][r] = 0.f;

    auto ldst = [&](int s, int buf) {
        const float* ag = A + (size_t)(m0 + srow) * lda + s * MBK + scol;
        const float* bg = B + (size_t)(n0 + srow) * ldb + s * MBK + scol;
        unsigned sa = (unsigned)__cvta_generic_to_shared(&As[buf][srow][scol]);
        unsigned sb = (unsigned)__cvta_generic_to_shared(&Bs[buf][srow][scol]);
        cp16(sa, ag); cp16(sa + 16, ag + 4);
        cp16(sb, bg); cp16(sb + 16, bg + 4);
    };

    ldst(0, 0);
    asm volatile("cp.async.commit_group;");

    const int nst = K / MBK;
    int buf = 0;
    for (int s = 0; s < nst; ++s) {
        if (s + 1 < nst) {
            ldst(s + 1, buf ^ 1);
            asm volatile("cp.async.commit_group;");
            asm volatile("cp.async.wait_group 1;");
        } else {
            asm volatile("cp.async.wait_group 0;");
        }
        __syncthreads();

#pragma unroll
        for (int kk = 0; kk < 2; ++kk) {
            const int k0 = kk * 8;
            unsigned a[4][4], b[4][2];
#pragma unroll
            for (int mi = 0; mi < 4; ++mi) {
                int r0 = wm + mi * 16 + gid;
                a[mi][0] = *(const unsigned*)&As[buf][r0][k0 + tig];
                a[mi][1] = *(const unsigned*)&As[buf][r0 + 8][k0 + tig];
                a[mi][2] = *(const unsigned*)&As[buf][r0][k0 + tig + 4];
                a[mi][3] = *(const unsigned*)&As[buf][r0 + 8][k0 + tig + 4];
            }
#pragma unroll
            for (int ni = 0; ni < 4; ++ni) {
                int r = wn + ni * 8 + gid;
                b[ni][0] = *(const unsigned*)&Bs[buf][r][k0 + tig];
                b[ni][1] = *(const unsigned*)&Bs[buf][r][k0 + tig + 4];
            }
#pragma unroll
            for (int mi = 0; mi < 4; ++mi)
#pragma unroll
                for (int ni = 0; ni < 4; ++ni)
                    mma8(acc[mi][ni], a[mi], b[ni]);
        }
        __syncthreads();
        buf ^= 1;
    }

#pragma unroll
    for (int ni = 0; ni < 4; ++ni) {
        int c0 = n0 + wn + ni * 8 + tig * 2;
        float2 bb = make_float2(0.f, 0.f);
        if (bias) bb = *reinterpret_cast<const float2*>(&bias[c0]);
#pragma unroll
        for (int mi = 0; mi < 4; ++mi) {
            int r = m0 + wm + mi * 16 + gid;
            *reinterpret_cast<float2*>(&C[(size_t)r * ldc + c0]) =
                make_float2(acc[mi][ni][0] + bb.x, acc[mi][ni][1] + bb.y);
            *reinterpret_cast<float2*>(&C[(size_t)(r + 8) * ldc + c0]) =
                make_float2(acc[mi][ni][2] + bb.x, acc[mi][ni][3] + bb.y);
        }
    }
}

// ---------------- warp-per-(token,half) top-32 of 512 ---------------------------
__global__ void topk_warp_kernel(const float* __restrict__ scores,
                                 float* __restrict__ t1v, int* __restrict__ t1i,
                                 float* __restrict__ t2v, int* __restrict__ t2i)
{
    int g = (blockIdx.x * blockDim.x + threadIdx.x) >> 5;
    int lane = threadIdx.x & 31;
    int token = g >> 1;
    int which = g & 1;
    const float* src = scores + (size_t)token * DIM + which * HALF;
    float* outv = (which ? t2v : t1v) + (size_t)token * TOPK;
    int*   outi = (which ? t2i : t1i) + (size_t)token * TOPK;

    float v[16];
#pragma unroll
    for (int j = 0; j < 16; j++) v[j] = src[j * 32 + lane];

    float lm = v[0]; int lj = 0;
#pragma unroll
    for (int j = 1; j < 16; j++)
        if (v[j] > lm) { lm = v[j]; lj = j; }

    for (int it = 0; it < TOPK; ++it) {
        float bv = lm;
        int bi = lj * 32 + lane;
#pragma unroll
        for (int s = 16; s > 0; s >>= 1) {
            float ov = __shfl_xor_sync(0xffffffffu, bv, s);
            int   oi = __shfl_xor_sync(0xffffffffu, bi, s);
            if (ov > bv || (ov == bv && oi < bi)) { bv = ov; bi = oi; }
        }
        if (lane == 0) { outv[it] = bv; outi[it] = bi; }
        if ((bi & 31) == lane) {
            int jd = bi >> 5;
#pragma unroll
            for (int j = 0; j < 16; j++)
                if (j == jd) v[j] = -INFINITY;
            lm = -INFINITY; lj = 0;
#pragma unroll
            for (int j = 0; j < 16; j++)
                if (v[j] > lm) { lm = v[j]; lj = j; }
        }
    }
}

// ---------------- fused: combine 32x32 topk + softmax + gather + silu gate ------
__global__ void combine_gather_kernel(const float* __restrict__ t1v, const int* __restrict__ t1i,
                                      const float* __restrict__ t2v, const int* __restrict__ t2i,
                                      const float* __restrict__ values,
                                      const float* __restrict__ gatepre,
                                      float* __restrict__ midh)
{
    const int token = blockIdx.x;
    const int tid = threadIdx.x;
    const int lane = tid & 31;
    const int wid = tid >> 5;

    __shared__ float s1v[TOPK], s2v[TOPK];
    __shared__ int   s1i[TOPK], s2i[TOPK];
    __shared__ float w[TOPK];
    __shared__ int   id[TOPK];

    if (tid < TOPK) {
        s1v[tid] = t1v[(size_t)token * TOPK + tid];
        s2v[tid] = t2v[(size_t)token * TOPK + tid];
        s1i[tid] = t1i[(size_t)token * TOPK + tid];
        s2i[tid] = t2i[(size_t)token * TOPK + tid];
    }
    __syncthreads();

    if (wid == 0) {
        float c[32];
        float s2l = s2v[lane];
#pragma unroll
        for (int a = 0; a < 32; a++) c[a] = s1v[a] + s2l;

        float lm = c[0]; int la = 0;
#pragma unroll
        for (int a = 1; a < 32; a++)
            if (c[a] > lm) { lm = c[a]; la = a; }

        for (int it = 0; it < TOPK; ++it) {
            float bv = lm;
            int bp = la * 32 + lane;
#pragma unroll
            for (int s = 16; s > 0; s >>= 1) {
                float ov = __shfl_xor_sync(0xffffffffu, bv, s);
                int   op = __shfl_xor_sync(0xffffffffu, bp, s);
                if (ov > bv || (ov == bv && op < bp)) { bv = ov; bp = op; }
            }
            if (lane == 0) {
                w[it] = bv;
                id[it] = s1i[bp >> 5] * NUM_KEYS + s2i[bp & 31];
            }
            if ((bp & 31) == lane) {
                int ad = bp >> 5;
#pragma unroll
                for (int a = 0; a < 32; a++)
                    if (a == ad) c[a] = -INFINITY;
                lm = -INFINITY; la = 0;
#pragma unroll
                for (int a = 0; a < 32; a++)
                    if (c[a] > lm) { lm = c[a]; la = a; }
            }
            __syncwarp();
        }
        float v = w[lane] * (1.0f / 32.0f);
        float mx = v;
#pragma unroll
        for (int s = 16; s > 0; s >>= 1) mx = fmaxf(mx, __shfl_xor_sync(0xffffffffu, mx, s));
        float e = expf(v - mx);
        float sum = e;
#pragma unroll
        for (int s = 16; s > 0; s >>= 1) sum += __shfl_xor_sync(0xffffffffu, sum, s);
        __syncwarp();
        w[lane] = e / sum;
    }
    __syncthreads();

    float4 acc = make_float4(0.f, 0.f, 0.f, 0.f);
#pragma unroll 8
    for (int k = 0; k < TOPK; ++k) {
        float wk = w[k];
        const float4* row = reinterpret_cast<const float4*>(values + (size_t)id[k] * DIM);
        float4 r = __ldg(&row[tid]);
        acc.x = fmaf(wk, r.x, acc.x);
        acc.y = fmaf(wk, r.y, acc.y);
        acc.z = fmaf(wk, r.z, acc.z);
        acc.w = fmaf(wk, r.w, acc.w);
    }
    float4 gp = reinterpret_cast<const float4*>(gatepre + (size_t)token * DIM)[tid];
    float4 o;
    o.x = tf32f(acc.x * (gp.x / (1.f + expf(-gp.x))));
    o.y = tf32f(acc.y * (gp.y / (1.f + expf(-gp.y))));
    o.z = tf32f(acc.z * (gp.z / (1.f + expf(-gp.z))));
    o.w = tf32f(acc.w * (gp.w / (1.f + expf(-gp.w))));
    reinterpret_cast<float4*>(midh + (size_t)token * DIM)[tid] = o;
}

// ---------------- launch ---------------------------------------------------------
extern "C" void kernel_launch(void* const* d_in, const int* in_sizes, int n_in,
                              void* d_out, int out_size)
{
    const float* x      = (const float*)d_in[0];
    const float* ke1    = (const float*)d_in[1];
    const float* ke2    = (const float*)d_in[2];
    const float* values = (const float*)d_in[3];
    const float* Wq     = (const float*)d_in[4];
    const float* bq     = (const float*)d_in[5];
    const float* Wg     = (const float*)d_in[6];
    const float* bg     = (const float*)d_in[7];
    const float* Wo     = (const float*)d_in[8];
    const float* bo     = (const float*)d_in[9];
    float* out = (float*)d_out;

    float *xh, *wgh, *woh, *M, *c, *scores, *gatepre, *midh, *t1v, *t2v;
    int *t1i, *t2i;
    cudaGetSymbolAddress((void**)&xh,  g_xh);
    cudaGetSymbolAddress((void**)&wgh, g_wgh);
    cudaGetSymbolAddress((void**)&woh, g_woh);
    cudaGetSymbolAddress((void**)&M,   g_M);
    cudaGetSymbolAddress((void**)&c,   g_c);
    cudaGetSymbolAddress((void**)&scores, g_scores);
    cudaGetSymbolAddress((void**)&gatepre, g_gatepre);
    cudaGetSymbolAddress((void**)&midh, g_midh);
    cudaGetSymbolAddress((void**)&t1v, g_t1v);
    cudaGetSymbolAddress((void**)&t1i, g_t1i);
    cudaGetSymbolAddress((void**)&t2v, g_t2v);
    cudaGetSymbolAddress((void**)&t2i, g_t2i);

    dim3 blk(256);

    // tf32 pre-round for smooth path
    prep_kernel<<<(P4_TOT + 255) / 256, blk>>>(
        (const float4*)x, (const float4*)Wg, (const float4*)Wo,
        (float4*)xh, (float4*)wgh, (float4*)woh);
    // folded bias c[k] = ke_half[k] . bq_half (exact; bq is zero in dataset)
    cfold_kernel<<<(DIM * 32) / 256, blk>>>(ke1, ke2, bq, c);
    // folded key matrix M = [ke1 @ Wq_top ; ke2 @ Wq_bot]  (fp32 exact)
    mprep_kernel<<<dim3(DIM / 64, DIM / 64), blk>>>(ke1, ke2, Wq, M);

    // scores = x @ M^T + c   (fp32 exact, one 4096x1024x1024 GEMM)
    gemm_tn2<<<dim3(DIM / BN, TOKENS / BM), blk>>>(x, DIM, M, DIM, scores, DIM, c, DIM);

    // gatepre = x @ Wg^T + bg (tf32 tensor cores)
    gemm_mma_tf32<<<dim3(DIM / BN, TOKENS / BM), blk>>>(xh, DIM, wgh, DIM, gatepre, DIM, bg, DIM);

    topk_warp_kernel<<<(2 * TOKENS) / 8, blk>>>(scores, t1v, t1i, t2v, t2i);
    combine_gather_kernel<<<TOKENS, blk>>>(t1v, t1i, t2v, t2i, values, gatepre, midh);

    // out = mid @ Wo^T + bo (tf32 tensor cores)
    gemm_mma_tf32<<<dim3(DIM / BN, TOKENS / BM), blk>>>(midh, DIM, woh, DIM, out, DIM, bo, DIM);
}